// round 9
// baseline (speedup 1.0000x reference)
#include <cuda_runtime.h>
#include <cuda_fp16.h>
#include <cstdint>

// ============================================================================
// LPDecoder: out[e] = sigmoid( relu( [z[s]|z[d]] @ W1 + b1 ) @ W2 + b2 )
//
// UV = z @ [W1_top | W1_bot] + [b1 | 0]   (fp16 m16n8k16 MMA, fp32 accum)
// out[e] = sigmoid( relu(UV[s][0:128] + UV[d][128:256]) . W2 + b2 )
//
// R9: edge kernel 8-lanes-per-edge (8 edges/warp-iter, 3-shfl reduction,
//     8 LDG.128 in flight). GEMM A fragments via ldmatrix.x4.
// ============================================================================

#define N_NODES_MAX 100000
#define SAP2 136            // sA row stride in halves (272B, 16B-aligned)

static __device__ __half g_UV[(size_t)N_NODES_MAX * 256];  // 51.2 MB scratch
static __device__ __half g_W1t[256 * 128];                 // 64 KB: [n_out][k]

// ----------------------------------------------------------------------------
// Prep: g_W1t[nout*128 + k] = (half) W1[ (nout>>7)*128 + k ][ nout&127 ]
// ----------------------------------------------------------------------------
__global__ void __launch_bounds__(256)
prep_w1(const float* __restrict__ W1)
{
    int idx = blockIdx.x * blockDim.x + threadIdx.x;   // 32768 total
    if (idx >= 256 * 128) return;
    int nout = idx >> 7;                  // 0..255
    int k    = idx & 127;                 // 0..127
    int r    = ((nout >> 7) << 7) + k;    // W1 row
    int c    = nout & 127;                // W1 col
    g_W1t[nout * 128 + k] = __float2half_rn(W1[r * 128 + c]);
}

// ----------------------------------------------------------------------------
// Kernel 1: UV[m][by*128+n] = sum_k z[m][k]*W1[by*128+k][n]  (+b1[n] for by=0)
// Block 256 thr (8 warps, 2x4), tile M=128 x N=256 (both halves), K=128.
// sA: [128][SAP2] halves, A fragments via ldmatrix.x4. B: LDG from g_W1t.
// ----------------------------------------------------------------------------
#define SMEM_HALVES (128 * SAP2)

__global__ void __launch_bounds__(256, 2)
gemm_uv(const float* __restrict__ z, const float* __restrict__ b1, int M)
{
    extern __shared__ __half smemh[];
    __half* sA = smemh;                 // [128][SAP2]

    const int tid = threadIdx.x;
    const int m0  = blockIdx.x * 128;

    // ---- Load A tile: z[m0..m0+127][0..127] -> fp16 sA ----
    #pragma unroll
    for (int it = 0; it < 16; ++it) {
        int idx = tid + it * 256;        // float4 index, 4096 total
        int r   = idx >> 5;
        int c4  = (idx & 31) << 2;
        float4 v = make_float4(0.f, 0.f, 0.f, 0.f);
        if (m0 + r < M)
            v = *(const float4*)(z + (size_t)(m0 + r) * 128 + c4);
        __half2* dst = (__half2*)(sA + r * SAP2 + c4);
        dst[0] = __floats2half2_rn(v.x, v.y);
        dst[1] = __floats2half2_rn(v.z, v.w);
    }
    __syncthreads();

    const int w     = tid >> 5;
    const int lane  = tid & 31;
    const int g     = lane >> 2;   // groupID 0..7
    const int tig   = lane & 3;    // 0..3
    const int wr    = w >> 2;      // 0/1 -> rows wr*64 ..
    const int wc    = w & 3;       // cols wc*32 ..
    const int n0w   = wc * 32;
    const int rbase = wr * 64;

    // ldmatrix per-lane addressing: tile t = lane>>3 (0..3), row-in-tile r.
    const int lm_t   = lane >> 3;
    const int lm_r   = lane & 7;
    const int lm_row = (lm_t & 1) * 8 + lm_r;   // + rbase + mt*16
    const int lm_k   = (lm_t >> 1) * 8;         // + kt*16
    const uint32_t sA_base =
        (uint32_t)__cvta_generic_to_shared(sA);

    #pragma unroll
    for (int by = 0; by < 2; ++by) {
        const __half* Bh = g_W1t + (size_t)by * 128 * 128;

        float c[4][4][4];
        #pragma unroll
        for (int mt = 0; mt < 4; ++mt)
            #pragma unroll
            for (int nt = 0; nt < 4; ++nt)
                #pragma unroll
                for (int i = 0; i < 4; ++i) c[mt][nt][i] = 0.f;

        #pragma unroll
        for (int kt = 0; kt < 8; ++kt) {
            const int ks = kt * 16 + 2 * tig;
            uint32_t bf[4][2];
            #pragma unroll
            for (int nt = 0; nt < 4; ++nt) {
                int n = n0w + nt * 8 + g;
                bf[nt][0] = *(const uint32_t*)(Bh + n * 128 + ks);
                bf[nt][1] = *(const uint32_t*)(Bh + n * 128 + ks + 8);
            }
            #pragma unroll
            for (int mt = 0; mt < 4; ++mt) {
                uint32_t addr = sA_base +
                    (uint32_t)(((rbase + mt * 16 + lm_row) * SAP2 +
                                kt * 16 + lm_k) * 2);
                uint32_t a0, a1, a2, a3;
                asm volatile(
                    "ldmatrix.sync.aligned.m8n8.x4.shared.b16 "
                    "{%0,%1,%2,%3}, [%4];"
                    : "=r"(a0), "=r"(a1), "=r"(a2), "=r"(a3)
                    : "r"(addr));
                #pragma unroll
                for (int nt = 0; nt < 4; ++nt) {
                    asm volatile(
                        "mma.sync.aligned.m16n8k16.row.col.f32.f16.f16.f32 "
                        "{%0,%1,%2,%3}, {%4,%5,%6,%7}, {%8,%9}, {%0,%1,%2,%3};"
                        : "+f"(c[mt][nt][0]), "+f"(c[mt][nt][1]),
                          "+f"(c[mt][nt][2]), "+f"(c[mt][nt][3])
                        : "r"(a0), "r"(a1), "r"(a2), "r"(a3),
                          "r"(bf[nt][0]), "r"(bf[nt][1]));
                }
            }
        }

        // ---- Epilogue: (+b1 if by==0), write fp16 UV ----
        #pragma unroll
        for (int mt = 0; mt < 4; ++mt) {
            int row0 = m0 + rbase + mt * 16 + g;
            int row1 = row0 + 8;
            #pragma unroll
            for (int nt = 0; nt < 4; ++nt) {
                int coln = n0w + nt * 8 + 2 * tig;
                float bx = 0.f, byv = 0.f;
                if (by == 0) {
                    float2 bb = *(const float2*)(b1 + coln);
                    bx = bb.x; byv = bb.y;
                }
                int colg = by * 128 + coln;
                if (row0 < M)
                    *(__half2*)(g_UV + (size_t)row0 * 256 + colg) =
                        __floats2half2_rn(c[mt][nt][0] + bx, c[mt][nt][1] + byv);
                if (row1 < M)
                    *(__half2*)(g_UV + (size_t)row1 * 256 + colg) =
                        __floats2half2_rn(c[mt][nt][2] + bx, c[mt][nt][3] + byv);
            }
        }
    }
}

// ----------------------------------------------------------------------------
// Kernel 2: 8 lanes per edge, 8 edges per warp-iteration.
// Lane covers 16 dims (2 x uint4). b1 folded into UV. Dot = two 4-term fp16
// chains summed in fp32. Reduction: 3 shfls within 8-lane groups.
// ----------------------------------------------------------------------------
__device__ __forceinline__ float dot16(uint4 u0, uint4 u1, uint4 v0, uint4 v1,
                                       const __half2* w)
{
    const __half2 z2 = __half2half2(__ushort_as_half(0));

    __half2 h0 = __hmax2(__hadd2(*(__half2*)&u0.x, *(__half2*)&v0.x), z2);
    __half2 h1 = __hmax2(__hadd2(*(__half2*)&u0.y, *(__half2*)&v0.y), z2);
    __half2 h2 = __hmax2(__hadd2(*(__half2*)&u0.z, *(__half2*)&v0.z), z2);
    __half2 h3 = __hmax2(__hadd2(*(__half2*)&u0.w, *(__half2*)&v0.w), z2);
    __half2 h4 = __hmax2(__hadd2(*(__half2*)&u1.x, *(__half2*)&v1.x), z2);
    __half2 h5 = __hmax2(__hadd2(*(__half2*)&u1.y, *(__half2*)&v1.y), z2);
    __half2 h6 = __hmax2(__hadd2(*(__half2*)&u1.z, *(__half2*)&v1.z), z2);
    __half2 h7 = __hmax2(__hadd2(*(__half2*)&u1.w, *(__half2*)&v1.w), z2);

    __half2 accA = __hmul2(h0, w[0]);
    accA = __hfma2(h1, w[1], accA);
    accA = __hfma2(h2, w[2], accA);
    accA = __hfma2(h3, w[3], accA);
    __half2 accB = __hmul2(h4, w[4]);
    accB = __hfma2(h5, w[5], accB);
    accB = __hfma2(h6, w[6], accB);
    accB = __hfma2(h7, w[7], accB);

    float2 fA = __half22float2(accA);
    float2 fB = __half22float2(accB);
    return (fA.x + fA.y) + (fB.x + fB.y);
}

__global__ void __launch_bounds__(256)
edge_kernel(const int* __restrict__ ei,
            const float* __restrict__ W2,
            const float* __restrict__ b2,
            float* __restrict__ out, int E)
{
    const int lane = threadIdx.x & 31;
    const int grp  = lane >> 3;          // edge slot 0..3 within warp
    const int gl   = lane & 7;           // lane within 8-lane group
    const int cb   = gl * 16;            // 16 halves per lane

    const int gwarp  = (blockIdx.x * blockDim.x + threadIdx.x) >> 5;
    const int nwarps = (gridDim.x * blockDim.x) >> 5;

    __half2 w[8];
    #pragma unroll
    for (int i = 0; i < 8; ++i) {
        float2 f = *(const float2*)(W2 + cb + 2 * i);
        w[i] = __floats2half2_rn(f.x, f.y);
    }
    const float bias2 = b2[0];

    for (int e0 = gwarp * 8; e0 < E; e0 += nwarps * 8) {
        int eA = e0 + grp;
        int eB = e0 + 4 + grp;
        bool vA = eA < E;
        bool vB = eB < E;

        int sA_ = vA ? ei[eA] : 0;
        int dA_ = vA ? ei[E + eA] : 0;
        int sB_ = vB ? ei[eB] : 0;
        int dB_ = vB ? ei[E + eB] : 0;

        const __half* uAp = g_UV + (size_t)sA_ * 256 + cb;
        const __half* vAp = g_UV + (size_t)dA_ * 256 + 128 + cb;
        const __half* uBp = g_UV + (size_t)sB_ * 256 + cb;
        const __half* vBp = g_UV + (size_t)dB_ * 256 + 128 + cb;

        uint4 ua0 = *(const uint4*)(uAp);
        uint4 ua1 = *(const uint4*)(uAp + 8);
        uint4 va0 = *(const uint4*)(vAp);
        uint4 va1 = *(const uint4*)(vAp + 8);
        uint4 ub0 = *(const uint4*)(uBp);
        uint4 ub1 = *(const uint4*)(uBp + 8);
        uint4 vb0 = *(const uint4*)(vBp);
        uint4 vb1 = *(const uint4*)(vBp + 8);

        float pA = dot16(ua0, ua1, va0, va1, w);
        float pB = dot16(ub0, ub1, vb0, vb1, w);

        #pragma unroll
        for (int off = 4; off > 0; off >>= 1) {
            pA += __shfl_xor_sync(0xffffffffu, pA, off);
            pB += __shfl_xor_sync(0xffffffffu, pB, off);
        }

        if (gl == 0) {
            if (vA) out[eA] = 1.0f / (1.0f + __expf(-(pA + bias2)));
            if (vB) out[eB] = 1.0f / (1.0f + __expf(-(pB + bias2)));
        }
    }
}

// ----------------------------------------------------------------------------
extern "C" void kernel_launch(void* const* d_in, const int* in_sizes, int n_in,
                              void* d_out, int out_size)
{
    const float* z   = (const float*)d_in[0];
    const int*   ei  = (const int*)d_in[1];
    const float* W1  = (const float*)d_in[2];
    const float* b1  = (const float*)d_in[3];
    const float* W2  = (const float*)d_in[4];
    const float* b2  = (const float*)d_in[5];
    float*       out = (float*)d_out;

    int M = in_sizes[0] / 128;   // nodes
    int E = in_sizes[1] / 2;     // edges

    const int smem_bytes = SMEM_HALVES * sizeof(__half);  // 34,816 B
    cudaFuncSetAttribute(gemm_uv, cudaFuncAttributeMaxDynamicSharedMemorySize,
                         smem_bytes);

    prep_w1<<<128, 256>>>(W1);
    gemm_uv<<<(M + 127) / 128, 256, smem_bytes>>>(z, b1, M);
    edge_kernel<<<1184, 256>>>(ei, W2, b2, out, E);
}